// round 7
// baseline (speedup 1.0000x reference)
#include <cuda_runtime.h>

#define B_SZ   512
#define F_SZ   512
#define NK     50
#define DK     16
#define NCOL   (NK*DK)     // 800
#define OUTW   (F_SZ + NK) // 562
#define KSPLIT 16
#define KCHUNK (F_SZ / KSPLIT)   // 32
#define ACT_SZ (B_SZ * NCOL)

__device__ float g_act_part[KSPLIT * ACT_SZ];  // split-K partials (m-major)
__device__ float g_act_T[NCOL * B_SZ];         // reduced, TRANSPOSED: [n][m]

// 10 tile-pairs (I<=J) over 4 row-tiles of 128
__constant__ int PAIR_I[10] = {0,0,0,0,1,1,1,2,2,3};
__constant__ int PAIR_J[10] = {0,1,2,3,1,2,3,2,3,3};

// ---------------------------------------------------------------------------
// GEMM split-K: act_part[kc][m][n] = sum_{k in chunk kc} x[m][k] * W[k][n]
// 64x64 tile, 256 threads, 4x4 micro-tile, grid (13, 8, 16).
// ---------------------------------------------------------------------------
__global__ __launch_bounds__(256) void gemm_kernel(const float* __restrict__ A,
                                                   const float* __restrict__ Bm) {
    __shared__ float As[16][64];
    __shared__ float Bs[16][64];

    const int tid = threadIdx.x;
    const int m0  = blockIdx.y * 64;
    const int n0  = blockIdx.x * 64;
    const int kc  = blockIdx.z;
    float* out = g_act_part + kc * ACT_SZ;

    const int ty = tid >> 4;
    const int tx = tid & 15;

    float acc[4][4] = {};

    const int kbeg = kc * KCHUNK;
    for (int k0 = kbeg; k0 < kbeg + KCHUNK; k0 += 16) {
        #pragma unroll
        for (int p = 0; p < 4; p++) {
            int e = tid + p * 256;
            int r = e >> 4, c = e & 15;
            As[c][r] = A[(m0 + r) * F_SZ + (k0 + c)];
        }
        #pragma unroll
        for (int p = 0; p < 4; p++) {
            int e = tid + p * 256;
            int r = e >> 6, c = e & 63;
            int n = n0 + c;
            Bs[r][c] = (n < NCOL) ? Bm[(k0 + r) * NCOL + n] : 0.0f;
        }
        __syncthreads();

        #pragma unroll
        for (int kk = 0; kk < 16; kk++) {
            float a[4], b[4];
            #pragma unroll
            for (int i = 0; i < 4; i++) a[i] = As[kk][ty * 4 + i];
            #pragma unroll
            for (int j = 0; j < 4; j++) b[j] = Bs[kk][tx * 4 + j];
            #pragma unroll
            for (int i = 0; i < 4; i++)
                #pragma unroll
                for (int j = 0; j < 4; j++)
                    acc[i][j] += a[i] * b[j];
        }
        __syncthreads();
    }

    #pragma unroll
    for (int i = 0; i < 4; i++) {
        int m = m0 + ty * 4 + i;
        #pragma unroll
        for (int j = 0; j < 4; j++) {
            int n = n0 + tx * 4 + j;
            if (n < NCOL) out[m * NCOL + n] = acc[i][j];
        }
    }
}

// ---------------------------------------------------------------------------
// Reduce 16 split-K partials AND transpose: g_act_T[n][m] = sum_p part[p][m][n]
// 32x32 tiles, smem transpose, coalesced both sides. grid (16, 25).
// ---------------------------------------------------------------------------
__global__ __launch_bounds__(256) void reduce_T_kernel() {
    __shared__ float t[32][33];
    const int tm0 = blockIdx.x * 32;   // m tile
    const int tn0 = blockIdx.y * 32;   // n tile
    const int c = threadIdx.x & 31;
    const int r = threadIdx.x >> 5;    // 0..7

    #pragma unroll
    for (int q = 0; q < 4; q++) {
        int mi = r * 4 + q;
        int idx = (tm0 + mi) * NCOL + tn0 + c;   // coalesced over c
        float s = 0.0f;
        #pragma unroll
        for (int p = 0; p < KSPLIT; p++) s += g_act_part[p * ACT_SZ + idx];
        t[mi][c] = s;
    }
    __syncthreads();
    #pragma unroll
    for (int q = 0; q < 4; q++) {
        int ni = r * 4 + q;
        g_act_T[(tn0 + ni) * B_SZ + tm0 + c] = t[c][ni];   // coalesced over c
    }
}

// ---------------------------------------------------------------------------
// Copy x into out[:,0:512] and ZERO out[:,512:562]
// ---------------------------------------------------------------------------
__global__ __launch_bounds__(256) void prep_out_kernel(const float* __restrict__ x,
                                                       float* __restrict__ out) {
    int idx = blockIdx.x * 256 + threadIdx.x;   // 512*281 = 143872 exactly
    int b = idx / 281, j = idx - b * 281;
    float2 v;
    if (j < 256) v = ((const float2*)(x + (size_t)b * F_SZ))[j];
    else         v = make_float2(0.0f, 0.0f);
    ((float2*)(out + (size_t)b * OUTW))[j] = v;
}

// ---------------------------------------------------------------------------
// Symmetric pairwise, 32-col chunks, broadcast smem reads, smem-atomic cols.
// grid = (40, 50): blockIdx.x = pair*4 + chunk. block = 128 threads.
// Thread t owns row I*128+t (16 coalesced LDG.32 from g_act_T).
// J-chunk staged as sJ[col][16] (16B-aligned rows -> broadcast LDS.128).
// Off-diag column sums: atomicAdd to per-warp smem slot (warp-uniform addr
// -> ptxas REDUX-aggregate), then cross-warp merge + one global atomic/col.
// ---------------------------------------------------------------------------
__global__ __launch_bounds__(128) void pairwise_kernel(float* __restrict__ out) {
    __shared__ float sJ[32][16];       // 2 KB: 32 cols x 16 d, rows 64B-aligned
    __shared__ float scol[4][32];      // per-warp column partials

    const int bx   = blockIdx.x;
    const int pair = bx >> 2;
    const int c0   = (bx & 3) * 32;    // column-chunk base within J tile
    const int I = PAIR_I[pair];
    const int J = PAIR_J[pair];
    const int k    = blockIdx.y;
    const int tid  = threadIdx.x;
    const int lane = tid & 31;
    const int w    = tid >> 5;

    // stage J chunk: 32 cols x 16 d (read float4 along m from g_act_T)
    {
        int d  = tid >> 3;          // 0..15
        int m4 = (tid & 7) * 4;     // 0,4,...,28
        float4 v = *(const float4*)(g_act_T + (k * DK + d) * B_SZ + J * 128 + c0 + m4);
        sJ[m4 + 0][d] = v.x;
        sJ[m4 + 1][d] = v.y;
        sJ[m4 + 2][d] = v.z;
        sJ[m4 + 3][d] = v.w;
    }
    scol[w][lane] = 0.0f;

    // own row: 16 coalesced scalar loads
    float a[16];
    const int rowB = I * 128 + tid;
    #pragma unroll
    for (int d = 0; d < 16; d++)
        a[d] = g_act_T[(k * DK + d) * B_SZ + rowB];
    __syncthreads();

    const bool diag = (I == J);
    float rowAcc = 0.0f;

    #pragma unroll 4
    for (int b2 = 0; b2 < 32; b2++) {
        const float4* vp = (const float4*)sJ[b2];   // broadcast, conflict-free
        float4 v0 = vp[0], v1 = vp[1], v2 = vp[2], v3 = vp[3];
        float p0 = fabsf(a[0]  - v0.x) + fabsf(a[1]  - v0.y)
                 + fabsf(a[2]  - v0.z) + fabsf(a[3]  - v0.w);
        float p1 = fabsf(a[4]  - v1.x) + fabsf(a[5]  - v1.y)
                 + fabsf(a[6]  - v1.z) + fabsf(a[7]  - v1.w);
        float p2 = fabsf(a[8]  - v2.x) + fabsf(a[9]  - v2.y)
                 + fabsf(a[10] - v2.z) + fabsf(a[11] - v2.w);
        float p3 = fabsf(a[12] - v3.x) + fabsf(a[13] - v3.y)
                 + fabsf(a[14] - v3.z) + fabsf(a[15] - v3.w);
        float e = __expf(-((p0 + p1) + (p2 + p3)));
        rowAcc += e;
        if (!diag)
            atomicAdd(&scol[w][b2], e);   // warp-uniform addr -> REDUX+1 ATOMS
    }

    float* fbase = out + F_SZ + k;
    atomicAdd(fbase + (size_t)rowB * OUTW, rowAcc);

    if (!diag) {
        __syncthreads();
        if (tid < 32) {
            float cs = scol[0][tid] + scol[1][tid]
                     + scol[2][tid] + scol[3][tid];
            atomicAdd(fbase + (size_t)(J * 128 + c0 + tid) * OUTW, cs);
        }
    }
}

// ---------------------------------------------------------------------------
extern "C" void kernel_launch(void* const* d_in, const int* in_sizes, int n_in,
                              void* d_out, int out_size) {
    const float* x = (const float*)d_in[0];
    const float* W = (const float*)d_in[1];
    float* out = (float*)d_out;

    dim3 gemm_grid((NCOL + 63) / 64, B_SZ / 64, KSPLIT);   // 13 x 8 x 16
    gemm_kernel<<<gemm_grid, 256>>>(x, W);

    dim3 red_grid(B_SZ / 32, NCOL / 32);                   // 16 x 25
    reduce_T_kernel<<<red_grid, 256>>>();

    prep_out_kernel<<<562, 256>>>(x, out);                 // copy + zero

    dim3 pw_grid(40, NK);                                  // 40 x 50 = 2000
    pairwise_kernel<<<pw_grid, 128>>>(out);
}

// round 8
// speedup vs baseline: 2.5459x; 2.5459x over previous
#include <cuda_runtime.h>

#define B_SZ   512
#define F_SZ   512
#define NK     50
#define DK     16
#define NCOL   (NK*DK)     // 800
#define OUTW   (F_SZ + NK) // 562
#define KSPLIT 8
#define KCHUNK (F_SZ / KSPLIT)   // 64
#define ACT_SZ (B_SZ * NCOL)

__device__ float g_act_part[KSPLIT * ACT_SZ];  // split-K partials (m-major)
__device__ float g_act_T[NCOL * B_SZ];         // reduced, TRANSPOSED: [n][m]

// 10 tile-pairs (I<=J) over 4 row-tiles of 128
__constant__ int PAIR_I[10] = {0,0,0,0,1,1,1,2,2,3};
__constant__ int PAIR_J[10] = {0,1,2,3,1,2,3,2,3,3};

// ---------------------------------------------------------------------------
// GEMM split-K: act_part[kc][m][n] = sum_{k in chunk kc} x[m][k] * W[k][n]
// ---------------------------------------------------------------------------
__global__ __launch_bounds__(256) void gemm_kernel(const float* __restrict__ A,
                                                   const float* __restrict__ Bm) {
    __shared__ float As[16][64];
    __shared__ float Bs[16][64];

    const int tid = threadIdx.x;
    const int m0  = blockIdx.y * 64;
    const int n0  = blockIdx.x * 64;
    const int kc  = blockIdx.z;
    float* out = g_act_part + kc * ACT_SZ;

    const int ty = tid >> 4;
    const int tx = tid & 15;

    float acc[4][4] = {};

    const int kbeg = kc * KCHUNK;
    for (int k0 = kbeg; k0 < kbeg + KCHUNK; k0 += 16) {
        #pragma unroll
        for (int p = 0; p < 4; p++) {
            int e = tid + p * 256;
            int r = e >> 4, c = e & 15;
            As[c][r] = A[(m0 + r) * F_SZ + (k0 + c)];
        }
        #pragma unroll
        for (int p = 0; p < 4; p++) {
            int e = tid + p * 256;
            int r = e >> 6, c = e & 63;
            int n = n0 + c;
            Bs[r][c] = (n < NCOL) ? Bm[(k0 + r) * NCOL + n] : 0.0f;
        }
        __syncthreads();

        #pragma unroll
        for (int kk = 0; kk < 16; kk++) {
            float a[4], b[4];
            #pragma unroll
            for (int i = 0; i < 4; i++) a[i] = As[kk][ty * 4 + i];
            #pragma unroll
            for (int j = 0; j < 4; j++) b[j] = Bs[kk][tx * 4 + j];
            #pragma unroll
            for (int i = 0; i < 4; i++)
                #pragma unroll
                for (int j = 0; j < 4; j++)
                    acc[i][j] += a[i] * b[j];
        }
        __syncthreads();
    }

    #pragma unroll
    for (int i = 0; i < 4; i++) {
        int m = m0 + ty * 4 + i;
        #pragma unroll
        for (int j = 0; j < 4; j++) {
            int n = n0 + tx * 4 + j;
            if (n < NCOL) out[m * NCOL + n] = acc[i][j];
        }
    }
}

// ---------------------------------------------------------------------------
// Reduce 8 split-K partials AND transpose: g_act_T[n][m] = sum_p part[p][m][n]
// ---------------------------------------------------------------------------
__global__ __launch_bounds__(256) void reduce_T_kernel() {
    __shared__ float t[32][33];
    const int tm0 = blockIdx.x * 32;
    const int tn0 = blockIdx.y * 32;
    const int c = threadIdx.x & 31;
    const int r = threadIdx.x >> 5;

    #pragma unroll
    for (int q = 0; q < 4; q++) {
        int mi = r * 4 + q;
        int idx = (tm0 + mi) * NCOL + tn0 + c;
        float s = 0.0f;
        #pragma unroll
        for (int p = 0; p < KSPLIT; p++) s += g_act_part[p * ACT_SZ + idx];
        t[mi][c] = s;
    }
    __syncthreads();
    #pragma unroll
    for (int q = 0; q < 4; q++) {
        int ni = r * 4 + q;
        g_act_T[(tn0 + ni) * B_SZ + tm0 + c] = t[c][ni];
    }
}

// ---------------------------------------------------------------------------
// Copy x into out[:,0:512] and ZERO out[:,512:562]
// ---------------------------------------------------------------------------
__global__ __launch_bounds__(256) void prep_out_kernel(const float* __restrict__ x,
                                                       float* __restrict__ out) {
    int idx = blockIdx.x * 256 + threadIdx.x;
    int b = idx / 281, j = idx - b * 281;
    float2 v;
    if (j < 256) v = ((const float2*)(x + (size_t)b * F_SZ))[j];
    else         v = make_float2(0.0f, 0.0f);
    ((float2*)(out + (size_t)b * OUTW))[j] = v;
}

// ---------------------------------------------------------------------------
// Symmetric pairwise, 32-col chunks, broadcast smem reads.
// Off-diag column sums: stash e into padded e_smem[row][col] (conflict-free
// STS), then a transposed reduction pass (conflict-free LDS) -> 1 global
// atomic per column. No shfl chains, no contended atomics.
// grid = (40, 50), block = 128.
// ---------------------------------------------------------------------------
__global__ __launch_bounds__(128) void pairwise_kernel(float* __restrict__ out) {
    __shared__ float sJ[32][16];        // 2 KB: 32 cols x 16 d
    __shared__ float e_smem[128][33];   // 16.9 KB, padded: banks (row+col)%32
    __shared__ float scol[4][32];

    const int bx   = blockIdx.x;
    const int pair = bx >> 2;
    const int c0   = (bx & 3) * 32;
    const int I = PAIR_I[pair];
    const int J = PAIR_J[pair];
    const int k   = blockIdx.y;
    const int tid = threadIdx.x;

    // stage J chunk: 32 cols x 16 d (float4-coalesced from g_act_T)
    {
        int d  = tid >> 3;
        int m4 = (tid & 7) * 4;
        float4 v = *(const float4*)(g_act_T + (k * DK + d) * B_SZ + J * 128 + c0 + m4);
        sJ[m4 + 0][d] = v.x;
        sJ[m4 + 1][d] = v.y;
        sJ[m4 + 2][d] = v.z;
        sJ[m4 + 3][d] = v.w;
    }

    // own row: 16 coalesced scalar loads
    float a[16];
    const int rowB = I * 128 + tid;
    #pragma unroll
    for (int d = 0; d < 16; d++)
        a[d] = g_act_T[(k * DK + d) * B_SZ + rowB];
    __syncthreads();

    const bool diag = (I == J);
    float rowAcc = 0.0f;

    #pragma unroll 4
    for (int b2 = 0; b2 < 32; b2++) {
        const float4* vp = (const float4*)sJ[b2];   // broadcast, conflict-free
        float4 v0 = vp[0], v1 = vp[1], v2 = vp[2], v3 = vp[3];
        float p0 = fabsf(a[0]  - v0.x) + fabsf(a[1]  - v0.y)
                 + fabsf(a[2]  - v0.z) + fabsf(a[3]  - v0.w);
        float p1 = fabsf(a[4]  - v1.x) + fabsf(a[5]  - v1.y)
                 + fabsf(a[6]  - v1.z) + fabsf(a[7]  - v1.w);
        float p2 = fabsf(a[8]  - v2.x) + fabsf(a[9]  - v2.y)
                 + fabsf(a[10] - v2.z) + fabsf(a[11] - v2.w);
        float p3 = fabsf(a[12] - v3.x) + fabsf(a[13] - v3.y)
                 + fabsf(a[14] - v3.z) + fabsf(a[15] - v3.w);
        float e = __expf(-((p0 + p1) + (p2 + p3)));
        rowAcc += e;
        if (!diag)
            e_smem[tid][b2] = e;   // banks (tid+b2)%32: conflict-free
    }

    float* fbase = out + F_SZ + k;
    atomicAdd(fbase + (size_t)rowB * OUTW, rowAcc);

    if (!diag) {
        __syncthreads();
        // transposed reduction: thread (q=tid>>5, col=tid&31) sums 32 rows
        const int col = tid & 31;
        const int q   = tid >> 5;
        float cs = 0.0f;
        #pragma unroll 8
        for (int r = 0; r < 32; r++)
            cs += e_smem[q * 32 + r][col];   // lanes consecutive: conflict-free
        scol[q][col] = cs;
        __syncthreads();
        if (tid < 32) {
            float tot = scol[0][tid] + scol[1][tid]
                      + scol[2][tid] + scol[3][tid];
            atomicAdd(fbase + (size_t)(J * 128 + c0 + tid) * OUTW, tot);
        }
    }
}

// ---------------------------------------------------------------------------
extern "C" void kernel_launch(void* const* d_in, const int* in_sizes, int n_in,
                              void* d_out, int out_size) {
    const float* x = (const float*)d_in[0];
    const float* W = (const float*)d_in[1];
    float* out = (float*)d_out;

    dim3 gemm_grid((NCOL + 63) / 64, B_SZ / 64, KSPLIT);   // 13 x 8 x 8
    gemm_kernel<<<gemm_grid, 256>>>(x, W);

    dim3 red_grid(B_SZ / 32, NCOL / 32);                   // 16 x 25
    reduce_T_kernel<<<red_grid, 256>>>();

    prep_out_kernel<<<562, 256>>>(x, out);                 // copy + zero

    dim3 pw_grid(40, NK);                                  // 40 x 50 = 2000
    pairwise_kernel<<<pw_grid, 128>>>(out);
}

// round 10
// speedup vs baseline: 3.0008x; 1.1787x over previous
#include <cuda_runtime.h>

#define B_SZ   512
#define F_SZ   512
#define NK     50
#define DK     16
#define NCOL   (NK*DK)     // 800
#define OUTW   (F_SZ + NK) // 562
#define KSPLIT 8
#define KCHUNK (F_SZ / KSPLIT)   // 64
#define ACT_SZ (B_SZ * NCOL)

__device__ float g_act_part[KSPLIT * ACT_SZ];  // split-K partials (m-major)
__device__ float g_act_T[NCOL * B_SZ];         // reduced, TRANSPOSED: [n][m]

// 10 tile-pairs (I<=J) over 4 row-tiles of 128
__constant__ int PAIR_I[10] = {0,0,0,0,1,1,1,2,2,3};
__constant__ int PAIR_J[10] = {0,1,2,3,1,2,3,2,3,3};

// ---------------------------------------------------------------------------
// GEMM split-K, one-shot smem: whole 64(m)x64(k) A-chunk and 64(k)x64(n)
// B-chunk staged once, then 64 uninterrupted kk steps. grid (13, 8, 8).
// A fragment read as 4x LDS.32 (row stride 65 floats is NOT 16B aligned;
// addresses are warp-broadcast so scalar reads are conflict-free).
// ---------------------------------------------------------------------------
__global__ __launch_bounds__(256) void gemm_kernel(const float* __restrict__ A,
                                                   const float* __restrict__ Bm) {
    __shared__ float As[64][65];   // As[k][m], padded
    __shared__ float Bs[64][64];   // Bs[k][n], rows 16B-aligned

    const int tid = threadIdx.x;
    const int m0  = blockIdx.y * 64;
    const int n0  = blockIdx.x * 64;
    const int kc  = blockIdx.z;
    const int kbeg = kc * KCHUNK;
    float* out = g_act_part + kc * ACT_SZ;

    // ---- load A chunk 64x64 (4 float4 per thread), store transposed ----
    #pragma unroll
    for (int p = 0; p < 4; p++) {
        int idx = tid + p * 256;        // float4 index, 1024 total
        int r  = idx >> 4;              // m row 0..63
        int c4 = idx & 15;              // k group
        float4 v = *(const float4*)(A + (m0 + r) * F_SZ + kbeg + c4 * 4);
        As[c4 * 4 + 0][r] = v.x;
        As[c4 * 4 + 1][r] = v.y;
        As[c4 * 4 + 2][r] = v.z;
        As[c4 * 4 + 3][r] = v.w;
    }
    // ---- load B chunk 64x64 (4 float4 per thread), direct ----
    #pragma unroll
    for (int p = 0; p < 4; p++) {
        int idx = tid + p * 256;
        int r  = idx >> 4;              // k row 0..63
        int c4 = idx & 15;              // n group
        int n  = n0 + c4 * 4;
        float4 v = (n < NCOL) ? *(const float4*)(Bm + (kbeg + r) * NCOL + n)
                              : make_float4(0.f, 0.f, 0.f, 0.f);
        *(float4*)&Bs[r][c4 * 4] = v;
    }
    __syncthreads();

    const int ty = tid >> 4;
    const int tx = tid & 15;
    float acc[4][4] = {};

    #pragma unroll 16
    for (int kk = 0; kk < 64; kk++) {
        float a[4], b[4];
        a[0] = As[kk][ty * 4 + 0];      // scalar: alignment-safe, broadcast
        a[1] = As[kk][ty * 4 + 1];
        a[2] = As[kk][ty * 4 + 2];
        a[3] = As[kk][ty * 4 + 3];
        *(float4*)b = *(const float4*)&Bs[kk][tx * 4];   // 16B-aligned
        #pragma unroll
        for (int i = 0; i < 4; i++)
            #pragma unroll
            for (int j = 0; j < 4; j++)
                acc[i][j] += a[i] * b[j];
    }

    #pragma unroll
    for (int i = 0; i < 4; i++) {
        int m = m0 + ty * 4 + i;
        #pragma unroll
        for (int j = 0; j < 4; j++) {
            int n = n0 + tx * 4 + j;
            if (n < NCOL) out[m * NCOL + n] = acc[i][j];
        }
    }
}

// ---------------------------------------------------------------------------
// Reduce 8 split-K partials AND transpose: g_act_T[n][m] = sum_p part[p][m][n]
// ---------------------------------------------------------------------------
__global__ __launch_bounds__(256) void reduce_T_kernel() {
    __shared__ float t[32][33];
    const int tm0 = blockIdx.x * 32;
    const int tn0 = blockIdx.y * 32;
    const int c = threadIdx.x & 31;
    const int r = threadIdx.x >> 5;

    #pragma unroll
    for (int q = 0; q < 4; q++) {
        int mi = r * 4 + q;
        int idx = (tm0 + mi) * NCOL + tn0 + c;
        float s = 0.0f;
        #pragma unroll
        for (int p = 0; p < KSPLIT; p++) s += g_act_part[p * ACT_SZ + idx];
        t[mi][c] = s;
    }
    __syncthreads();
    #pragma unroll
    for (int q = 0; q < 4; q++) {
        int ni = r * 4 + q;
        g_act_T[(tn0 + ni) * B_SZ + tm0 + c] = t[c][ni];
    }
}

// ---------------------------------------------------------------------------
// Copy x into out[:,0:512] and ZERO out[:,512:562]
// ---------------------------------------------------------------------------
__global__ __launch_bounds__(256) void prep_out_kernel(const float* __restrict__ x,
                                                       float* __restrict__ out) {
    int idx = blockIdx.x * 256 + threadIdx.x;
    int b = idx / 281, j = idx - b * 281;
    float2 v;
    if (j < 256) v = ((const float2*)(x + (size_t)b * F_SZ))[j];
    else         v = make_float2(0.0f, 0.0f);
    ((float2*)(out + (size_t)b * OUTW))[j] = v;
}

// ---------------------------------------------------------------------------
// Symmetric pairwise (R8 winning version, unchanged).
// grid = (40, 50), block = 128.
// ---------------------------------------------------------------------------
__global__ __launch_bounds__(128) void pairwise_kernel(float* __restrict__ out) {
    __shared__ float sJ[32][16];        // 2 KB
    __shared__ float e_smem[128][33];   // 16.9 KB padded
    __shared__ float scol[4][32];

    const int bx   = blockIdx.x;
    const int pair = bx >> 2;
    const int c0   = (bx & 3) * 32;
    const int I = PAIR_I[pair];
    const int J = PAIR_J[pair];
    const int k   = blockIdx.y;
    const int tid = threadIdx.x;

    {
        int d  = tid >> 3;
        int m4 = (tid & 7) * 4;
        float4 v = *(const float4*)(g_act_T + (k * DK + d) * B_SZ + J * 128 + c0 + m4);
        sJ[m4 + 0][d] = v.x;
        sJ[m4 + 1][d] = v.y;
        sJ[m4 + 2][d] = v.z;
        sJ[m4 + 3][d] = v.w;
    }

    float a[16];
    const int rowB = I * 128 + tid;
    #pragma unroll
    for (int d = 0; d < 16; d++)
        a[d] = g_act_T[(k * DK + d) * B_SZ + rowB];
    __syncthreads();

    const bool diag = (I == J);
    float rowAcc = 0.0f;

    #pragma unroll 4
    for (int b2 = 0; b2 < 32; b2++) {
        const float4* vp = (const float4*)sJ[b2];
        float4 v0 = vp[0], v1 = vp[1], v2 = vp[2], v3 = vp[3];
        float p0 = fabsf(a[0]  - v0.x) + fabsf(a[1]  - v0.y)
                 + fabsf(a[2]  - v0.z) + fabsf(a[3]  - v0.w);
        float p1 = fabsf(a[4]  - v1.x) + fabsf(a[5]  - v1.y)
                 + fabsf(a[6]  - v1.z) + fabsf(a[7]  - v1.w);
        float p2 = fabsf(a[8]  - v2.x) + fabsf(a[9]  - v2.y)
                 + fabsf(a[10] - v2.z) + fabsf(a[11] - v2.w);
        float p3 = fabsf(a[12] - v3.x) + fabsf(a[13] - v3.y)
                 + fabsf(a[14] - v3.z) + fabsf(a[15] - v3.w);
        float e = __expf(-((p0 + p1) + (p2 + p3)));
        rowAcc += e;
        if (!diag)
            e_smem[tid][b2] = e;
    }

    float* fbase = out + F_SZ + k;
    atomicAdd(fbase + (size_t)rowB * OUTW, rowAcc);

    if (!diag) {
        __syncthreads();
        const int col = tid & 31;
        const int q   = tid >> 5;
        float cs = 0.0f;
        #pragma unroll 8
        for (int r = 0; r < 32; r++)
            cs += e_smem[q * 32 + r][col];
        scol[q][col] = cs;
        __syncthreads();
        if (tid < 32) {
            float tot = scol[0][tid] + scol[1][tid]
                      + scol[2][tid] + scol[3][tid];
            atomicAdd(fbase + (size_t)(J * 128 + c0 + tid) * OUTW, tot);
        }
    }
}

// ---------------------------------------------------------------------------
extern "C" void kernel_launch(void* const* d_in, const int* in_sizes, int n_in,
                              void* d_out, int out_size) {
    const float* x = (const float*)d_in[0];
    const float* W = (const float*)d_in[1];
    float* out = (float*)d_out;

    dim3 gemm_grid((NCOL + 63) / 64, B_SZ / 64, KSPLIT);   // 13 x 8 x 8
    gemm_kernel<<<gemm_grid, 256>>>(x, W);

    dim3 red_grid(B_SZ / 32, NCOL / 32);                   // 16 x 25
    reduce_T_kernel<<<red_grid, 256>>>();

    prep_out_kernel<<<562, 256>>>(x, out);                 // copy + zero

    dim3 pw_grid(40, NK);                                  // 40 x 50 = 2000
    pairwise_kernel<<<pw_grid, 128>>>(out);
}

// round 11
// speedup vs baseline: 3.0357x; 1.0116x over previous
#include <cuda_runtime.h>

#define B_SZ   512
#define F_SZ   512
#define NK     50
#define DK     16
#define NCOL   (NK*DK)     // 800
#define OUTW   (F_SZ + NK) // 562
#define KSPLIT 8
#define KCHUNK (F_SZ / KSPLIT)   // 64
#define ACT_SZ (B_SZ * NCOL)

__device__ float g_act_part[KSPLIT * ACT_SZ];  // split-K partials (m-major)
__device__ float g_act_T[NCOL * B_SZ];         // reduced, TRANSPOSED: [n][m]

// 10 tile-pairs (I<=J) over 4 row-tiles of 128
__constant__ int PAIR_I[10] = {0,0,0,0,1,1,1,2,2,3};
__constant__ int PAIR_J[10] = {0,1,2,3,1,2,3,2,3,3};

// ---------------------------------------------------------------------------
// GEMM split-K, one-shot smem. grid (13, 8, 8) = 832 blocks.
// launch_bounds(256,6): <=42 regs -> 6 CTAs/SM -> 888 capacity -> ONE wave.
// ---------------------------------------------------------------------------
__global__ __launch_bounds__(256, 6) void gemm_kernel(const float* __restrict__ A,
                                                      const float* __restrict__ Bm) {
    __shared__ float As[64][65];   // As[k][m], padded (scalar reads, broadcast)
    __shared__ float Bs[64][64];   // Bs[k][n], rows 16B-aligned

    const int tid = threadIdx.x;
    const int m0  = blockIdx.y * 64;
    const int n0  = blockIdx.x * 64;
    const int kc  = blockIdx.z;
    const int kbeg = kc * KCHUNK;
    float* out = g_act_part + kc * ACT_SZ;

    // ---- load A chunk 64x64 (4 float4 per thread), store transposed ----
    #pragma unroll
    for (int p = 0; p < 4; p++) {
        int idx = tid + p * 256;        // float4 index, 1024 total
        int r  = idx >> 4;              // m row 0..63
        int c4 = idx & 15;              // k group
        float4 v = *(const float4*)(A + (m0 + r) * F_SZ + kbeg + c4 * 4);
        As[c4 * 4 + 0][r] = v.x;
        As[c4 * 4 + 1][r] = v.y;
        As[c4 * 4 + 2][r] = v.z;
        As[c4 * 4 + 3][r] = v.w;
    }
    // ---- load B chunk 64x64 (4 float4 per thread), direct ----
    #pragma unroll
    for (int p = 0; p < 4; p++) {
        int idx = tid + p * 256;
        int r  = idx >> 4;              // k row 0..63
        int c4 = idx & 15;              // n group
        int n  = n0 + c4 * 4;
        float4 v = (n < NCOL) ? *(const float4*)(Bm + (kbeg + r) * NCOL + n)
                              : make_float4(0.f, 0.f, 0.f, 0.f);
        *(float4*)&Bs[r][c4 * 4] = v;
    }
    __syncthreads();

    const int ty = tid >> 4;
    const int tx = tid & 15;
    float acc[4][4] = {};

    #pragma unroll 16
    for (int kk = 0; kk < 64; kk++) {
        float a[4], b[4];
        a[0] = As[kk][ty * 4 + 0];      // scalar: alignment-safe, broadcast
        a[1] = As[kk][ty * 4 + 1];
        a[2] = As[kk][ty * 4 + 2];
        a[3] = As[kk][ty * 4 + 3];
        *(float4*)b = *(const float4*)&Bs[kk][tx * 4];   // 16B-aligned
        #pragma unroll
        for (int i = 0; i < 4; i++)
            #pragma unroll
            for (int j = 0; j < 4; j++)
                acc[i][j] += a[i] * b[j];
    }

    #pragma unroll
    for (int i = 0; i < 4; i++) {
        int m = m0 + ty * 4 + i;
        #pragma unroll
        for (int j = 0; j < 4; j++) {
            int n = n0 + tx * 4 + j;
            if (n < NCOL) out[m * NCOL + n] = acc[i][j];
        }
    }
}

// ---------------------------------------------------------------------------
// MERGED: reduce+transpose (blocks 0..399) and prep_out (blocks 400..961).
//   reduce:  g_act_T[n][m] = sum_p part[p][m][n], 32x32 smem transpose tiles
//   prep:    out[:,0:512] = x; out[:,512:562] = 0
// ---------------------------------------------------------------------------
__global__ __launch_bounds__(256) void epilogue_kernel(const float* __restrict__ x,
                                                       float* __restrict__ out) {
    const int bx = blockIdx.x;
    if (bx < 400) {
        __shared__ float t[32][33];
        const int tm0 = (bx & 15) * 32;          // 16 m tiles
        const int tn0 = (bx >> 4) * 32;          // 25 n tiles
        const int c = threadIdx.x & 31;
        const int r = threadIdx.x >> 5;

        #pragma unroll
        for (int q = 0; q < 4; q++) {
            int mi = r * 4 + q;
            int idx = (tm0 + mi) * NCOL + tn0 + c;
            float s = 0.0f;
            #pragma unroll
            for (int p = 0; p < KSPLIT; p++) s += g_act_part[p * ACT_SZ + idx];
            t[mi][c] = s;
        }
        __syncthreads();
        #pragma unroll
        for (int q = 0; q < 4; q++) {
            int ni = r * 4 + q;
            g_act_T[(tn0 + ni) * B_SZ + tm0 + c] = t[c][ni];
        }
    } else {
        int idx = (bx - 400) * 256 + threadIdx.x;   // 562*256 = 143872 exactly
        int b = idx / 281, j = idx - b * 281;
        float2 v;
        if (j < 256) v = ((const float2*)(x + (size_t)b * F_SZ))[j];
        else         v = make_float2(0.0f, 0.0f);
        ((float2*)(out + (size_t)b * OUTW))[j] = v;
    }
}

// ---------------------------------------------------------------------------
// Symmetric pairwise (R8 winning version, unchanged).
// grid = (40, 50), block = 128.
// ---------------------------------------------------------------------------
__global__ __launch_bounds__(128) void pairwise_kernel(float* __restrict__ out) {
    __shared__ float sJ[32][16];        // 2 KB
    __shared__ float e_smem[128][33];   // 16.9 KB padded
    __shared__ float scol[4][32];

    const int bx   = blockIdx.x;
    const int pair = bx >> 2;
    const int c0   = (bx & 3) * 32;
    const int I = PAIR_I[pair];
    const int J = PAIR_J[pair];
    const int k   = blockIdx.y;
    const int tid = threadIdx.x;

    {
        int d  = tid >> 3;
        int m4 = (tid & 7) * 4;
        float4 v = *(const float4*)(g_act_T + (k * DK + d) * B_SZ + J * 128 + c0 + m4);
        sJ[m4 + 0][d] = v.x;
        sJ[m4 + 1][d] = v.y;
        sJ[m4 + 2][d] = v.z;
        sJ[m4 + 3][d] = v.w;
    }

    float a[16];
    const int rowB = I * 128 + tid;
    #pragma unroll
    for (int d = 0; d < 16; d++)
        a[d] = g_act_T[(k * DK + d) * B_SZ + rowB];
    __syncthreads();

    const bool diag = (I == J);
    float rowAcc = 0.0f;

    #pragma unroll 4
    for (int b2 = 0; b2 < 32; b2++) {
        const float4* vp = (const float4*)sJ[b2];
        float4 v0 = vp[0], v1 = vp[1], v2 = vp[2], v3 = vp[3];
        float p0 = fabsf(a[0]  - v0.x) + fabsf(a[1]  - v0.y)
                 + fabsf(a[2]  - v0.z) + fabsf(a[3]  - v0.w);
        float p1 = fabsf(a[4]  - v1.x) + fabsf(a[5]  - v1.y)
                 + fabsf(a[6]  - v1.z) + fabsf(a[7]  - v1.w);
        float p2 = fabsf(a[8]  - v2.x) + fabsf(a[9]  - v2.y)
                 + fabsf(a[10] - v2.z) + fabsf(a[11] - v2.w);
        float p3 = fabsf(a[12] - v3.x) + fabsf(a[13] - v3.y)
                 + fabsf(a[14] - v3.z) + fabsf(a[15] - v3.w);
        float e = __expf(-((p0 + p1) + (p2 + p3)));
        rowAcc += e;
        if (!diag)
            e_smem[tid][b2] = e;
    }

    float* fbase = out + F_SZ + k;
    atomicAdd(fbase + (size_t)rowB * OUTW, rowAcc);

    if (!diag) {
        __syncthreads();
        const int col = tid & 31;
        const int q   = tid >> 5;
        float cs = 0.0f;
        #pragma unroll 8
        for (int r = 0; r < 32; r++)
            cs += e_smem[q * 32 + r][col];
        scol[q][col] = cs;
        __syncthreads();
        if (tid < 32) {
            float tot = scol[0][tid] + scol[1][tid]
                      + scol[2][tid] + scol[3][tid];
            atomicAdd(fbase + (size_t)(J * 128 + c0 + tid) * OUTW, tot);
        }
    }
}

// ---------------------------------------------------------------------------
extern "C" void kernel_launch(void* const* d_in, const int* in_sizes, int n_in,
                              void* d_out, int out_size) {
    const float* x = (const float*)d_in[0];
    const float* W = (const float*)d_in[1];
    float* out = (float*)d_out;

    dim3 gemm_grid((NCOL + 63) / 64, B_SZ / 64, KSPLIT);   // 13 x 8 x 8
    gemm_kernel<<<gemm_grid, 256>>>(x, W);

    epilogue_kernel<<<962, 256>>>(x, out);   // reduce_T (400) + prep (562)

    dim3 pw_grid(40, NK);                    // 40 x 50 = 2000
    pairwise_kernel<<<pw_grid, 128>>>(out);
}

// round 12
// speedup vs baseline: 3.0570x; 1.0070x over previous
#include <cuda_runtime.h>

#define B_SZ   512
#define F_SZ   512
#define NK     50
#define DK     16
#define NCOL   (NK*DK)     // 800
#define OUTW   (F_SZ + NK) // 562
#define KSPLIT 8
#define KCHUNK (F_SZ / KSPLIT)   // 64
#define ACT_SZ (B_SZ * NCOL)

__device__ float g_act_part[KSPLIT * ACT_SZ];  // split-K partials (m-major)
__device__ float g_act_T[NCOL * B_SZ];         // reduced, TRANSPOSED: [n][m]

// 10 tile-pairs (I<=J) over 4 row-tiles of 128
__constant__ int PAIR_I[10] = {0,0,0,0,1,1,1,2,2,3};
__constant__ int PAIR_J[10] = {0,1,2,3,1,2,3,2,3,3};

// ---------------------------------------------------------------------------
// GEMM split-K, one-shot smem, K-vectorized inner loop.
// A stored m-major (As[m][k]): float4 STS conflict-free, LDS.128 reads are
// 2-address warp broadcasts. Per 4 kk-steps: 8 LDS.128 + 64 FFMA.
// grid (13, 8, 8) = 832 blocks; (256,6) -> 6 CTAs/SM -> single wave.
// ---------------------------------------------------------------------------
__global__ __launch_bounds__(256, 6) void gemm_kernel(const float* __restrict__ A,
                                                      const float* __restrict__ Bm) {
    __shared__ float As[64][64];   // As[m][k]
    __shared__ float Bs[64][64];   // Bs[k][n]

    const int tid = threadIdx.x;
    const int m0  = blockIdx.y * 64;
    const int n0  = blockIdx.x * 64;
    const int kc  = blockIdx.z;
    const int kbeg = kc * KCHUNK;
    float* out = g_act_part + kc * ACT_SZ;

    // ---- load A chunk 64(m)x64(k): direct float4 copy, no transpose ----
    #pragma unroll
    for (int p = 0; p < 4; p++) {
        int idx = tid + p * 256;        // float4 index, 1024 total
        int r  = idx >> 4;              // m row 0..63
        int c4 = idx & 15;              // k group
        float4 v = *(const float4*)(A + (m0 + r) * F_SZ + kbeg + c4 * 4);
        *(float4*)&As[r][c4 * 4] = v;   // consecutive 16B: conflict-free
    }
    // ---- load B chunk 64(k)x64(n): direct float4 copy ----
    #pragma unroll
    for (int p = 0; p < 4; p++) {
        int idx = tid + p * 256;
        int r  = idx >> 4;              // k row 0..63
        int c4 = idx & 15;              // n group
        int n  = n0 + c4 * 4;
        float4 v = (n < NCOL) ? *(const float4*)(Bm + (kbeg + r) * NCOL + n)
                              : make_float4(0.f, 0.f, 0.f, 0.f);
        *(float4*)&Bs[r][c4 * 4] = v;
    }
    __syncthreads();

    const int ty = tid >> 4;
    const int tx = tid & 15;
    float acc[4][4] = {};

    #pragma unroll 4
    for (int k4 = 0; k4 < 16; k4++) {
        float a_reg[4][4];              // a_reg[i][j] = A[m=ty*4+i][k=k4*4+j]
        #pragma unroll
        for (int i = 0; i < 4; i++)
            *(float4*)a_reg[i] = *(const float4*)&As[ty * 4 + i][k4 * 4];
        #pragma unroll
        for (int j = 0; j < 4; j++) {
            float b[4];
            *(float4*)b = *(const float4*)&Bs[k4 * 4 + j][tx * 4];
            #pragma unroll
            for (int i = 0; i < 4; i++)
                #pragma unroll
                for (int n = 0; n < 4; n++)
                    acc[i][n] += a_reg[i][j] * b[n];
        }
    }

    #pragma unroll
    for (int i = 0; i < 4; i++) {
        int m = m0 + ty * 4 + i;
        #pragma unroll
        for (int j = 0; j < 4; j++) {
            int n = n0 + tx * 4 + j;
            if (n < NCOL) out[m * NCOL + n] = acc[i][j];
        }
    }
}

// ---------------------------------------------------------------------------
// MERGED: reduce+transpose (blocks 0..399) and prep_out (blocks 400..961).
// ---------------------------------------------------------------------------
__global__ __launch_bounds__(256) void epilogue_kernel(const float* __restrict__ x,
                                                       float* __restrict__ out) {
    const int bx = blockIdx.x;
    if (bx < 400) {
        __shared__ float t[32][33];
        const int tm0 = (bx & 15) * 32;          // 16 m tiles
        const int tn0 = (bx >> 4) * 32;          // 25 n tiles
        const int c = threadIdx.x & 31;
        const int r = threadIdx.x >> 5;

        #pragma unroll
        for (int q = 0; q < 4; q++) {
            int mi = r * 4 + q;
            int idx = (tm0 + mi) * NCOL + tn0 + c;
            float s = 0.0f;
            #pragma unroll
            for (int p = 0; p < KSPLIT; p++) s += g_act_part[p * ACT_SZ + idx];
            t[mi][c] = s;
        }
        __syncthreads();
        #pragma unroll
        for (int q = 0; q < 4; q++) {
            int ni = r * 4 + q;
            g_act_T[(tn0 + ni) * B_SZ + tm0 + c] = t[c][ni];
        }
    } else {
        int idx = (bx - 400) * 256 + threadIdx.x;   // 562*256 = 143872 exactly
        int b = idx / 281, j = idx - b * 281;
        float2 v;
        if (j < 256) v = ((const float2*)(x + (size_t)b * F_SZ))[j];
        else         v = make_float2(0.0f, 0.0f);
        ((float2*)(out + (size_t)b * OUTW))[j] = v;
    }
}

// ---------------------------------------------------------------------------
// Symmetric pairwise (R8 winning version, unchanged).
// grid = (40, 50), block = 128.
// ---------------------------------------------------------------------------
__global__ __launch_bounds__(128) void pairwise_kernel(float* __restrict__ out) {
    __shared__ float sJ[32][16];        // 2 KB
    __shared__ float e_smem[128][33];   // 16.9 KB padded
    __shared__ float scol[4][32];

    const int bx   = blockIdx.x;
    const int pair = bx >> 2;
    const int c0   = (bx & 3) * 32;
    const int I = PAIR_I[pair];
    const int J = PAIR_J[pair];
    const int k   = blockIdx.y;
    const int tid = threadIdx.x;

    {
        int d  = tid >> 3;
        int m4 = (tid & 7) * 4;
        float4 v = *(const float4*)(g_act_T + (k * DK + d) * B_SZ + J * 128 + c0 + m4);
        sJ[m4 + 0][d] = v.x;
        sJ[m4 + 1][d] = v.y;
        sJ[m4 + 2][d] = v.z;
        sJ[m4 + 3][d] = v.w;
    }

    float a[16];
    const int rowB = I * 128 + tid;
    #pragma unroll
    for (int d = 0; d < 16; d++)
        a[d] = g_act_T[(k * DK + d) * B_SZ + rowB];
    __syncthreads();

    const bool diag = (I == J);
    float rowAcc = 0.0f;

    #pragma unroll 4
    for (int b2 = 0; b2 < 32; b2++) {
        const float4* vp = (const float4*)sJ[b2];
        float4 v0 = vp[0], v1 = vp[1], v2 = vp[2], v3 = vp[3];
        float p0 = fabsf(a[0]  - v0.x) + fabsf(a[1]  - v0.y)
                 + fabsf(a[2]  - v0.z) + fabsf(a[3]  - v0.w);
        float p1 = fabsf(a[4]  - v1.x) + fabsf(a[5]  - v1.y)
                 + fabsf(a[6]  - v1.z) + fabsf(a[7]  - v1.w);
        float p2 = fabsf(a[8]  - v2.x) + fabsf(a[9]  - v2.y)
                 + fabsf(a[10] - v2.z) + fabsf(a[11] - v2.w);
        float p3 = fabsf(a[12] - v3.x) + fabsf(a[13] - v3.y)
                 + fabsf(a[14] - v3.z) + fabsf(a[15] - v3.w);
        float e = __expf(-((p0 + p1) + (p2 + p3)));
        rowAcc += e;
        if (!diag)
            e_smem[tid][b2] = e;
    }

    float* fbase = out + F_SZ + k;
    atomicAdd(fbase + (size_t)rowB * OUTW, rowAcc);

    if (!diag) {
        __syncthreads();
        const int col = tid & 31;
        const int q   = tid >> 5;
        float cs = 0.0f;
        #pragma unroll 8
        for (int r = 0; r < 32; r++)
            cs += e_smem[q * 32 + r][col];
        scol[q][col] = cs;
        __syncthreads();
        if (tid < 32) {
            float tot = scol[0][tid] + scol[1][tid]
                      + scol[2][tid] + scol[3][tid];
            atomicAdd(fbase + (size_t)(J * 128 + c0 + tid) * OUTW, tot);
        }
    }
}

// ---------------------------------------------------------------------------
extern "C" void kernel_launch(void* const* d_in, const int* in_sizes, int n_in,
                              void* d_out, int out_size) {
    const float* x = (const float*)d_in[0];
    const float* W = (const float*)d_in[1];
    float* out = (float*)d_out;

    dim3 gemm_grid((NCOL + 63) / 64, B_SZ / 64, KSPLIT);   // 13 x 8 x 8
    gemm_kernel<<<gemm_grid, 256>>>(x, W);

    epilogue_kernel<<<962, 256>>>(x, out);   // reduce_T (400) + prep (562)

    dim3 pw_grid(40, NK);                    // 40 x 50 = 2000
    pairwise_kernel<<<pw_grid, 128>>>(out);
}